// round 8
// baseline (speedup 1.0000x reference)
#include <cuda_runtime.h>
#include <cuda_bf16.h>
#include <cstdint>

#define NB 65536
#define KK 20

// ---------------- device scratch (allocation-free rule) ----------------
__device__ __nv_bfloat16 g_Xhi[(size_t)NB * 448];
__device__ __nv_bfloat16 g_Xlo[(size_t)NB * 448];
__device__ __nv_bfloat16 g_H1hi[(size_t)NB * 256];
__device__ __nv_bfloat16 g_H1lo[(size_t)NB * 256];
__device__ __nv_bfloat16 g_W1Thi[256 * 448];
__device__ __nv_bfloat16 g_W1Tlo[256 * 448];
__device__ __nv_bfloat16 g_W2Thi[128 * 256];
__device__ __nv_bfloat16 g_W2Tlo[128 * 256];
__device__ __nv_bfloat16 g_W3Thi[64 * 128];
__device__ __nv_bfloat16 g_W3Tlo[64 * 128];

// ---------------- helpers ----------------
__device__ __forceinline__ uint32_t smem_u32(const void* p) {
    uint32_t a;
    asm("{ .reg .u64 t; cvta.to.shared.u64 t, %1; cvt.u32.u64 %0, t; }" : "=r"(a) : "l"(p));
    return a;
}
__device__ __forceinline__ void cpasync16(uint32_t s, const void* g) {
    asm volatile("cp.async.cg.shared.global [%0], [%1], 16;" :: "r"(s), "l"(g));
}
#define CP_COMMIT() asm volatile("cp.async.commit_group;" ::: "memory")
#define CP_WAIT(n)  asm volatile("cp.async.wait_group %0;" :: "n"(n) : "memory")

__device__ __forceinline__ void ldsm4(uint32_t* r, uint32_t addr) {
    asm volatile("ldmatrix.sync.aligned.m8n8.x4.shared.b16 {%0,%1,%2,%3}, [%4];"
        : "=r"(r[0]), "=r"(r[1]), "=r"(r[2]), "=r"(r[3]) : "r"(addr));
}
__device__ __forceinline__ void mma16816(float* c, const uint32_t* a, const uint32_t* b) {
    asm volatile("mma.sync.aligned.m16n8k16.row.col.f32.bf16.bf16.f32 "
        "{%0,%1,%2,%3}, {%4,%5,%6,%7}, {%8,%9}, {%0,%1,%2,%3};"
        : "+f"(c[0]), "+f"(c[1]), "+f"(c[2]), "+f"(c[3])
        : "r"(a[0]), "r"(a[1]), "r"(a[2]), "r"(a[3]), "r"(b[0]), "r"(b[1]));
}

__device__ __forceinline__ void bf16split(float v, __nv_bfloat16& h, __nv_bfloat16& l) {
    h = __float2bfloat16_rn(v);
    l = __float2bfloat16_rn(v - __bfloat162float(h));
}
__device__ __forceinline__ void store4(__nv_bfloat16* ph, __nv_bfloat16* pl, float4 v) {
    __nv_bfloat16 h0, l0, h1, l1, h2, l2, h3, l3;
    bf16split(v.x, h0, l0); bf16split(v.y, h1, l1);
    bf16split(v.z, h2, l2); bf16split(v.w, h3, l3);
    ((__nv_bfloat162*)ph)[0] = __nv_bfloat162(h0, h1);
    ((__nv_bfloat162*)ph)[1] = __nv_bfloat162(h2, h3);
    ((__nv_bfloat162*)pl)[0] = __nv_bfloat162(l0, l1);
    ((__nv_bfloat162*)pl)[1] = __nv_bfloat162(l2, l3);
}

// smem tile geometry: 128 rows x 32 bf16, padded row stride 40 (80B, conflict-free)
#define TROW     40
#define PLANE_B  (128 * TROW * 2)     // 10240 bytes
#define BUF_B    (4 * PLANE_B)        // A_hi A_lo B_hi B_lo = 40960
#define PIPE_B   (2 * BUF_B)          // 81920

// layer-3 smem geometry (h2 planes reuse pipe region; stride 136 bf16)
#define L3ROW    136
#define H2_PLANE (128 * L3ROW * 2)    // 34816 bytes (2 planes = 69632 <= PIPE_B)
#define G2_SUM   PIPE_B
#define G2_BYTES (PIPE_B + 512 + 128)

// ---------------------------------------------------------------------------
// Prep: transpose + bf16-split W1, W2, W3
// ---------------------------------------------------------------------------
__global__ void k_prep(const float* __restrict__ W1, const float* __restrict__ W2,
                       const float* __restrict__ W3) {
    int tid = blockIdx.x * blockDim.x + threadIdx.x;
    if (tid < 448 * 256) {
        int k = tid >> 8, n = tid & 255;
        __nv_bfloat16 h, l; bf16split(W1[tid], h, l);
        g_W1Thi[n * 448 + k] = h; g_W1Tlo[n * 448 + k] = l;
    } else if (tid < 448 * 256 + 256 * 128) {
        int t = tid - 448 * 256;
        int k = t >> 7, n = t & 127;
        __nv_bfloat16 h, l; bf16split(W2[t], h, l);
        g_W2Thi[n * 256 + k] = h; g_W2Tlo[n * 256 + k] = l;
    } else if (tid < 448 * 256 + 256 * 128 + 64 * 128) {
        int t = tid - (448 * 256 + 256 * 128);
        int n = t >> 7, k = t & 127;
        __nv_bfloat16 h, l; bf16split(W3[k * 64 + n], h, l);
        g_W3Thi[n * 128 + k] = h; g_W3Tlo[n * 128 + k] = l;
    }
}

// ---------------------------------------------------------------------------
// Assemble: X row = [eu | ei | mean_p | mean_t | mean_ik] -> bf16 hi/lo planes
// ---------------------------------------------------------------------------
__global__ __launch_bounds__(160) void k_assemble(
    const int* __restrict__ user, const int* __restrict__ item,
    const int* __restrict__ pk, const int* __restrict__ tk, const int* __restrict__ ik,
    const int* __restrict__ vp, const int* __restrict__ vt, const int* __restrict__ vi,
    const float* __restrict__ eu, const float* __restrict__ ei, const float* __restrict__ ek)
{
    int b = blockIdx.x;
    int w = threadIdx.x >> 5, lane = threadIdx.x & 31;
    __nv_bfloat16* Xh = g_Xhi + (size_t)b * 448;
    __nv_bfloat16* Xl = g_Xlo + (size_t)b * 448;

    if (w == 0) {
        float4 v = ((const float4*)(eu + (size_t)user[b] * 128))[lane];
        store4(Xh + lane * 4, Xl + lane * 4, v);
    } else if (w == 1) {
        float4 v = ((const float4*)(ei + (size_t)item[b] * 128))[lane];
        store4(Xh + 128 + lane * 4, Xl + 128 + lane * 4, v);
    } else {
        const int* idx; int valid; int off;
        if (w == 2)      { idx = pk; valid = vp[b]; off = 256; }
        else if (w == 3) { idx = tk; valid = vt[b]; off = 320; }
        else             { idx = ik; valid = vi[b]; off = 384; }
        int my_idx = (lane < KK) ? idx[b * KK + lane] : 0;
        int d = lane & 15, ko = lane >> 4;
        float4 acc = make_float4(0.f, 0.f, 0.f, 0.f);
        const int nIt = (valid + 1) >> 1;           // warp-uniform trip count
        for (int k2 = 0; k2 < nIt; k2++) {
            int k = k2 * 2 + ko;
            int r = __shfl_sync(0xffffffffu, my_idx, k < KK ? k : 0);
            if (k < valid) {
                float4 v = ((const float4*)(ek + (size_t)r * 64))[d];
                acc.x += v.x; acc.y += v.y; acc.z += v.z; acc.w += v.w;
            }
        }
        acc.x += __shfl_xor_sync(0xffffffffu, acc.x, 16);
        acc.y += __shfl_xor_sync(0xffffffffu, acc.y, 16);
        acc.z += __shfl_xor_sync(0xffffffffu, acc.z, 16);
        acc.w += __shfl_xor_sync(0xffffffffu, acc.w, 16);
        if (lane < 16) {
            float s = (valid > 0) ? (1.f / (float)valid) : 0.f;
            acc.x *= s; acc.y *= s; acc.z *= s; acc.w *= s;
            store4(Xh + off + d * 4, Xl + off + d * 4, acc);
        }
    }
}

// ---------------------------------------------------------------------------
// bf16x3 MMA core: CTA tile 128(M) x 128(N), K chunks of 32, double-buffered
// cp.async. 8 warps: wm = w&3 (M), wn = w>>2 (N). Warp tile 32x64.
// MMA issue is TERM-MAJOR: all 16 independent ah*bh first, then ah*bl, then
// al*bh -> accumulator reuse distance 16 (hides HMMA RAW latency).
// ---------------------------------------------------------------------------
template<int LDA, int LDB, int NC>
__device__ __forceinline__ void gemm_core(
    uint32_t sb,
    const __nv_bfloat16* __restrict__ Ahi, const __nv_bfloat16* __restrict__ Alo,
    const __nv_bfloat16* __restrict__ Bhi, const __nv_bfloat16* __restrict__ Blo,
    float acc[2][8][4])
{
    const int tid = threadIdx.x;
    const int lane = tid & 31, w = tid >> 5;
    const int wm = w & 3, wn = w >> 2;

    auto load_chunk = [&](int buf, int kc) {
        const uint32_t base = sb + buf * BUF_B;
        #pragma unroll
        for (int i = tid; i < 512; i += 256) {
            int row = i >> 2, seg = i & 3;
            uint32_t so = base + (uint32_t)(row * TROW + seg * 8) * 2;
            int go = kc * 32 + seg * 8;
            cpasync16(so,               Ahi + (size_t)row * LDA + go);
            cpasync16(so + PLANE_B,     Alo + (size_t)row * LDA + go);
            cpasync16(so + 2 * PLANE_B, Bhi + (size_t)row * LDB + go);
            cpasync16(so + 3 * PLANE_B, Blo + (size_t)row * LDB + go);
        }
        CP_COMMIT();
    };

    load_chunk(0, 0);

    for (int kc = 0; kc < NC; kc++) {
        if (kc + 1 < NC) { load_chunk((kc + 1) & 1, kc + 1); CP_WAIT(1); }
        else             { CP_WAIT(0); }
        __syncthreads();

        const uint32_t bA = sb + (kc & 1) * BUF_B;
        const uint32_t bB = bA + 2 * PLANE_B;
        #pragma unroll
        for (int ks = 0; ks < 2; ks++) {
            const int k0 = ks * 16;
            uint32_t aoff = (uint32_t)((wm * 32 + (lane & 15)) * TROW + k0 + (lane >> 4) * 8) * 2;
            uint32_t ah[2][4], al[2][4];
            ldsm4(ah[0], bA + aoff);
            ldsm4(ah[1], bA + aoff + 16 * TROW * 2);
            ldsm4(al[0], bA + PLANE_B + aoff);
            ldsm4(al[1], bA + PLANE_B + aoff + 16 * TROW * 2);

            const int q = lane >> 3;
            uint32_t brow0 = (uint32_t)(wn * 64 + (q >> 1) * 8 + (lane & 7));
            uint32_t bcol  = (uint32_t)(k0 + (q & 1) * 8);
            uint32_t bh[8][2], bl[8][2];
            #pragma unroll
            for (int p = 0; p < 4; p++) {
                uint32_t off = ((brow0 + p * 16) * TROW + bcol) * 2;
                uint32_t t[4];
                ldsm4(t, bB + off);
                bh[2*p][0] = t[0]; bh[2*p][1] = t[1];
                bh[2*p+1][0] = t[2]; bh[2*p+1][1] = t[3];
                ldsm4(t, bB + PLANE_B + off);
                bl[2*p][0] = t[0]; bl[2*p][1] = t[1];
                bl[2*p+1][0] = t[2]; bl[2*p+1][1] = t[3];
            }
            // term-major: 16 independent MMAs per term
            #pragma unroll
            for (int mt = 0; mt < 2; mt++)
                #pragma unroll
                for (int nt = 0; nt < 8; nt++)
                    mma16816(acc[mt][nt], ah[mt], bh[nt]);
            #pragma unroll
            for (int mt = 0; mt < 2; mt++)
                #pragma unroll
                for (int nt = 0; nt < 8; nt++)
                    mma16816(acc[mt][nt], ah[mt], bl[nt]);
            #pragma unroll
            for (int mt = 0; mt < 2; mt++)
                #pragma unroll
                for (int nt = 0; nt < 8; nt++)
                    mma16816(acc[mt][nt], al[mt], bh[nt]);
        }
        __syncthreads();
    }
}

// ---------------------------------------------------------------------------
// GEMM1: H1 = relu(X @ W1 + b1)   grid (512, 2)
// ---------------------------------------------------------------------------
__global__ __launch_bounds__(256, 2) void k_gemm1(const float* __restrict__ b1)
{
    extern __shared__ char smem[];
    const uint32_t sb = smem_u32(smem);
    const size_t rowBase = (size_t)blockIdx.x * 128;
    const int colBase = blockIdx.y * 128;

    float acc[2][8][4];
    #pragma unroll
    for (int a = 0; a < 2; a++)
        #pragma unroll
        for (int b = 0; b < 8; b++)
            #pragma unroll
            for (int c = 0; c < 4; c++) acc[a][b][c] = 0.f;

    gemm_core<448, 448, 14>(sb,
        g_Xhi + rowBase * 448, g_Xlo + rowBase * 448,
        g_W1Thi + (size_t)colBase * 448, g_W1Tlo + (size_t)colBase * 448, acc);

    const int tid = threadIdx.x, lane = tid & 31, w = tid >> 5;
    const int wm = w & 3, wn = w >> 2, grp = lane >> 2, tig = lane & 3;
    #pragma unroll
    for (int mt = 0; mt < 2; mt++) {
        const size_t r0 = rowBase + wm * 32 + mt * 16 + grp;
        #pragma unroll
        for (int nt = 0; nt < 8; nt++) {
            const int c = colBase + wn * 64 + nt * 8 + tig * 2;
            float bb0 = __ldg(b1 + c), bb1 = __ldg(b1 + c + 1);
            float v00 = fmaxf(acc[mt][nt][0] + bb0, 0.f);
            float v01 = fmaxf(acc[mt][nt][1] + bb1, 0.f);
            float v10 = fmaxf(acc[mt][nt][2] + bb0, 0.f);
            float v11 = fmaxf(acc[mt][nt][3] + bb1, 0.f);
            __nv_bfloat16 h0, l0, h1, l1;
            bf16split(v00, h0, l0); bf16split(v01, h1, l1);
            *(__nv_bfloat162*)(g_H1hi + r0 * 256 + c) = __nv_bfloat162(h0, h1);
            *(__nv_bfloat162*)(g_H1lo + r0 * 256 + c) = __nv_bfloat162(l0, l1);
            bf16split(v10, h0, l0); bf16split(v11, h1, l1);
            *(__nv_bfloat162*)(g_H1hi + (r0 + 8) * 256 + c) = __nv_bfloat162(h0, h1);
            *(__nv_bfloat162*)(g_H1lo + (r0 + 8) * 256 + c) = __nv_bfloat162(l0, l1);
        }
    }
}

// ---------------------------------------------------------------------------
// GEMM2 + MMA tail: h2 = relu(H1@W2+b2) -> smem bf16 planes;
// h3 = relu(h2@W3+b3) via bf16x3 HMMA (W3 frags direct from gmem/L1);
// out = h3@Wp + bp via reduction. smem ~82KB -> 2 CTAs/SM.
// ---------------------------------------------------------------------------
__global__ __launch_bounds__(256, 2) void k_gemm2_tail(
    const float* __restrict__ b2, const float* __restrict__ b3,
    const float* __restrict__ Wp, const float* __restrict__ bp,
    float* __restrict__ out)
{
    extern __shared__ char smem[];
    const uint32_t sb = smem_u32(smem);
    const int tid = threadIdx.x, lane = tid & 31, w = tid >> 5;
    const int wm = w & 3, wn = w >> 2, grp = lane >> 2, tig = lane & 3;
    const size_t rowBase = (size_t)blockIdx.x * 128;

    float acc[2][8][4];
    #pragma unroll
    for (int a = 0; a < 2; a++)
        #pragma unroll
        for (int b = 0; b < 8; b++)
            #pragma unroll
            for (int c = 0; c < 4; c++) acc[a][b][c] = 0.f;

    gemm_core<256, 256, 8>(sb,
        g_H1hi + rowBase * 256, g_H1lo + rowBase * 256,
        g_W2Thi, g_W2Tlo, acc);

    // h2 = relu(acc + b2) -> smem bf16 hi/lo planes (stride L3ROW), reusing pipe region
    __nv_bfloat16* h2hi = (__nv_bfloat16*)smem;
    __nv_bfloat16* h2lo = (__nv_bfloat16*)(smem + H2_PLANE);
    float* h3sum = (float*)(smem + G2_SUM);
    {
        #pragma unroll
        for (int mt = 0; mt < 2; mt++) {
            const int r = wm * 32 + mt * 16 + grp;
            #pragma unroll
            for (int nt = 0; nt < 8; nt++) {
                const int c = wn * 64 + nt * 8 + tig * 2;
                float bb0 = __ldg(b2 + c), bb1 = __ldg(b2 + c + 1);
                float v00 = fmaxf(acc[mt][nt][0] + bb0, 0.f);
                float v01 = fmaxf(acc[mt][nt][1] + bb1, 0.f);
                float v10 = fmaxf(acc[mt][nt][2] + bb0, 0.f);
                float v11 = fmaxf(acc[mt][nt][3] + bb1, 0.f);
                __nv_bfloat16 h0, l0, h1, l1;
                bf16split(v00, h0, l0); bf16split(v01, h1, l1);
                *(__nv_bfloat162*)(h2hi + r * L3ROW + c) = __nv_bfloat162(h0, h1);
                *(__nv_bfloat162*)(h2lo + r * L3ROW + c) = __nv_bfloat162(l0, l1);
                bf16split(v10, h0, l0); bf16split(v11, h1, l1);
                *(__nv_bfloat162*)(h2hi + (r + 8) * L3ROW + c) = __nv_bfloat162(h0, h1);
                *(__nv_bfloat162*)(h2lo + (r + 8) * L3ROW + c) = __nv_bfloat162(l0, l1);
            }
        }
    }
    if (tid < 128) h3sum[tid] = 0.f;
    __syncthreads();

    // layer 3 via bf16x3 HMMA: M=128, N=64 (wn covers 32 = 4 n-tiles), K=128.
    float acc3[2][4][4];
    #pragma unroll
    for (int a = 0; a < 2; a++)
        #pragma unroll
        for (int b = 0; b < 4; b++)
            #pragma unroll
            for (int c = 0; c < 4; c++) acc3[a][b][c] = 0.f;

    const uint32_t hA = sb;
    #pragma unroll
    for (int kc = 0; kc < 8; kc++) {
        const int k0 = kc * 16;
        uint32_t aoff = (uint32_t)((wm * 32 + (lane & 15)) * L3ROW + k0 + (lane >> 4) * 8) * 2;
        uint32_t ah[2][4], al[2][4];
        ldsm4(ah[0], hA + aoff);
        ldsm4(ah[1], hA + aoff + 16 * L3ROW * 2);
        ldsm4(al[0], hA + H2_PLANE + aoff);
        ldsm4(al[1], hA + H2_PLANE + aoff + 16 * L3ROW * 2);

        uint32_t bh[4][2], bl[4][2];
        #pragma unroll
        for (int nt = 0; nt < 4; nt++) {
            const int n = wn * 32 + nt * 8 + grp;
            const int base = n * 128 + k0 + tig * 2;
            bh[nt][0] = *(const uint32_t*)(g_W3Thi + base);
            bh[nt][1] = *(const uint32_t*)(g_W3Thi + base + 8);
            bl[nt][0] = *(const uint32_t*)(g_W3Tlo + base);
            bl[nt][1] = *(const uint32_t*)(g_W3Tlo + base + 8);
        }
        // term-major: 8 independent MMAs per term
        #pragma unroll
        for (int mt = 0; mt < 2; mt++)
            #pragma unroll
            for (int nt = 0; nt < 4; nt++)
                mma16816(acc3[mt][nt], ah[mt], bh[nt]);
        #pragma unroll
        for (int mt = 0; mt < 2; mt++)
            #pragma unroll
            for (int nt = 0; nt < 4; nt++)
                mma16816(acc3[mt][nt], ah[mt], bl[nt]);
        #pragma unroll
        for (int mt = 0; mt < 2; mt++)
            #pragma unroll
            for (int nt = 0; nt < 4; nt++)
                mma16816(acc3[mt][nt], al[mt], bh[nt]);
    }

    // head: relu(h3 + b3) . Wp, reduce to per-row sums
    {
        float rs[2][2] = {{0.f, 0.f}, {0.f, 0.f}};
        #pragma unroll
        for (int nt = 0; nt < 4; nt++) {
            const int c = wn * 32 + nt * 8 + tig * 2;
            float bb0 = __ldg(b3 + c),  bb1 = __ldg(b3 + c + 1);
            float wp0 = __ldg(Wp + c),  wp1 = __ldg(Wp + c + 1);
            #pragma unroll
            for (int mt = 0; mt < 2; mt++) {
                rs[mt][0] += fmaxf(acc3[mt][nt][0] + bb0, 0.f) * wp0
                           + fmaxf(acc3[mt][nt][1] + bb1, 0.f) * wp1;
                rs[mt][1] += fmaxf(acc3[mt][nt][2] + bb0, 0.f) * wp0
                           + fmaxf(acc3[mt][nt][3] + bb1, 0.f) * wp1;
            }
        }
        #pragma unroll
        for (int mt = 0; mt < 2; mt++)
            #pragma unroll
            for (int h = 0; h < 2; h++) {
                rs[mt][h] += __shfl_xor_sync(0xffffffffu, rs[mt][h], 1);
                rs[mt][h] += __shfl_xor_sync(0xffffffffu, rs[mt][h], 2);
            }
        if (tig == 0) {
            #pragma unroll
            for (int mt = 0; mt < 2; mt++) {
                atomicAdd(&h3sum[wm * 32 + mt * 16 + grp],     rs[mt][0]);
                atomicAdd(&h3sum[wm * 32 + mt * 16 + grp + 8], rs[mt][1]);
            }
        }
    }
    __syncthreads();
    if (tid < 128) out[rowBase + tid] = h3sum[tid] + __ldg(bp);
}

// ---------------------------------------------------------------------------
extern "C" void kernel_launch(void* const* d_in, const int* in_sizes, int n_in,
                              void* d_out, int out_size)
{
    const int*   user = (const int*)d_in[0];
    const int*   item = (const int*)d_in[1];
    const int*   pk   = (const int*)d_in[2];
    const int*   tk   = (const int*)d_in[3];
    const int*   ik   = (const int*)d_in[4];
    const int*   vp   = (const int*)d_in[5];
    const int*   vt   = (const int*)d_in[6];
    const int*   vi   = (const int*)d_in[7];
    const float* eu   = (const float*)d_in[8];
    const float* ei   = (const float*)d_in[9];
    const float* ek   = (const float*)d_in[10];
    const float* W1   = (const float*)d_in[11];
    const float* b1   = (const float*)d_in[12];
    const float* W2   = (const float*)d_in[13];
    const float* b2   = (const float*)d_in[14];
    const float* W3   = (const float*)d_in[15];
    const float* b3   = (const float*)d_in[16];
    const float* Wp   = (const float*)d_in[17];
    const float* bp   = (const float*)d_in[18];
    float* out = (float*)d_out;

    cudaFuncSetAttribute(k_gemm1,      cudaFuncAttributeMaxDynamicSharedMemorySize, PIPE_B);
    cudaFuncSetAttribute(k_gemm2_tail, cudaFuncAttributeMaxDynamicSharedMemorySize, G2_BYTES);

    const int prep_n = 448 * 256 + 256 * 128 + 64 * 128;
    k_prep<<<(prep_n + 255) / 256, 256>>>(W1, W2, W3);
    k_assemble<<<NB, 160>>>(user, item, pk, tk, ik, vp, vt, vi, eu, ei, ek);
    k_gemm1<<<dim3(NB / 128, 2), 256, PIPE_B>>>(b1);
    k_gemm2_tail<<<NB / 128, 256, G2_BYTES>>>(b2, b3, Wp, bp, out);
}